// round 4
// baseline (speedup 1.0000x reference)
#include <cuda_runtime.h>
#include <cuda_bf16.h>
#include <math.h>

// Problem constants
#define B_  64
#define T_  512
#define I_  512
#define H_  1024
#define G4  4096           // 4*H
#define BH  (B_*H_)        // 65536
#define NCTA 128
#define BKH 16             // k-chunk per stage per half-K group
#define NSTAGE 32          // 512 / 16 stages per group

typedef unsigned long long u64;
typedef unsigned int u32;

// ---------------------------------------------------------------------------
// Device scratch
// ---------------------------------------------------------------------------
__device__ float g_xp[(size_t)2 * T_ * B_ * G4];   // xp[dir][t][b][g]  (1 GiB)
__device__ float g_wT[2][H_][G4];                  // w_hh transposed [dir][k][n] (32 MB)
__device__ float g_hT[2][2][H_][B_];               // h: [phase][dir][j][b]
__device__ float g_cT[2][H_][B_];                  // c: [dir][j][b]
__device__ unsigned g_bar_count;
__device__ volatile unsigned g_bar_sense;

// ---------------------------------------------------------------------------
// PTX helpers
// ---------------------------------------------------------------------------
__device__ __forceinline__ void fma2(u64& c, u64 a, u64 b) {
    asm volatile("fma.rn.f32x2 %0, %1, %2, %0;" : "+l"(c) : "l"(a), "l"(b));
}
__device__ __forceinline__ u64 rep2(float x) {
    u64 r;
    asm volatile("mov.b64 %0, {%1, %1};" : "=l"(r) : "f"(x));
    return r;
}
__device__ __forceinline__ void cp_async16(u32 smem_addr, const void* gptr) {
    asm volatile("cp.async.cg.shared.global [%0], [%1], 16;" :: "r"(smem_addr), "l"(gptr));
}
__device__ __forceinline__ void cp_commit() { asm volatile("cp.async.commit_group;"); }
__device__ __forceinline__ void cp_wait(int n) {
    if (n == 2)      asm volatile("cp.async.wait_group 2;");
    else if (n == 1) asm volatile("cp.async.wait_group 1;");
    else             asm volatile("cp.async.wait_group 0;");
}
__device__ __forceinline__ float lo32(u64 v) { return __uint_as_float((u32)(v & 0xffffffffull)); }
__device__ __forceinline__ float hi32(u64 v) { return __uint_as_float((u32)(v >> 32)); }

// ---------------------------------------------------------------------------
// Init: zero h(phase 0), c, and barrier state (every replay!)
// ---------------------------------------------------------------------------
__global__ void init_state_kernel() {
    int i = blockIdx.x * blockDim.x + threadIdx.x;
    if (i < 2 * BH) {
        ((float*)g_hT)[i] = 0.0f;
        ((float*)g_cT)[i] = 0.0f;
    }
    if (i == 0) { g_bar_count = 0; g_bar_sense = 0; }
}

// ---------------------------------------------------------------------------
// Transpose w_hh [4096,1024] -> g_wT [dir][1024][4096]
// ---------------------------------------------------------------------------
__global__ void __launch_bounds__(256) transpose_w_kernel(
    const float* __restrict__ wfw, const float* __restrict__ wbw)
{
    __shared__ float tile[32][33];
    const int dir = blockIdx.z;
    const float* w = dir ? wbw : wfw;
    const int n0 = blockIdx.x * 32;
    const int k0 = blockIdx.y * 32;
    const int tx = threadIdx.x & 31, ty = threadIdx.x >> 5;
#pragma unroll
    for (int r = 0; r < 32; r += 8)
        tile[ty + r][tx] = w[(size_t)(n0 + ty + r) * H_ + k0 + tx];
    __syncthreads();
#pragma unroll
    for (int r = 0; r < 32; r += 8)
        g_wT[dir][k0 + ty + r][n0 + tx] = tile[tx][ty + r];
}

// ---------------------------------------------------------------------------
// Input projection (unchanged from R2)
// ---------------------------------------------------------------------------
__global__ void __launch_bounds__(128) input_proj_kernel(
    const float* __restrict__ x,
    const float* __restrict__ w_fw, const float* __restrict__ w_bw,
    const float* __restrict__ bi_fw, const float* __restrict__ bh_fw,
    const float* __restrict__ bi_bw, const float* __restrict__ bh_bw)
{
    const int gt  = blockIdx.x;
    const int t   = blockIdx.y;
    const int dir = blockIdx.z;

    const float* w     = dir ? w_bw : w_fw;
    const float* bi    = dir ? bi_bw : bi_fw;
    const float* bh    = dir ? bh_bw : bh_fw;
    const int    src_t = dir ? (T_ - 1 - t) : t;

    __shared__ float sA[16][68];
    __shared__ float sB[16][68];

    const int tid = threadIdx.x;
    const int tr  = tid >> 4;
    const int tc  = tid & 15;

    u64 acc[4][4];
#pragma unroll
    for (int p = 0; p < 4; p++)
#pragma unroll
        for (int j = 0; j < 4; j++) acc[p][j] = 0ull;

    const float* Abase = x + (size_t)src_t * I_;
    const float* Bbase = w + (size_t)(gt * 64) * I_;

    for (int k0 = 0; k0 < I_; k0 += 16) {
#pragma unroll 4
        for (int idx = tid; idx < 1024; idx += 128) {
            int kk = idx & 15, m = idx >> 4;
            sA[kk][m] = Abase[(size_t)m * (T_ * I_) + k0 + kk];
        }
#pragma unroll 4
        for (int idx = tid; idx < 1024; idx += 128) {
            int kk = idx & 15, n = idx >> 4;
            sB[kk][n] = Bbase[(size_t)n * I_ + k0 + kk];
        }
        __syncthreads();
#pragma unroll
        for (int kk = 0; kk < 16; kk++) {
            const float* ap = &sA[kk][tr * 8];
            u64 a0 = *(const u64*)(ap + 0);
            u64 a1 = *(const u64*)(ap + 2);
            u64 a2 = *(const u64*)(ap + 4);
            u64 a3 = *(const u64*)(ap + 6);
            float4 b4 = *(const float4*)&sB[kk][tc * 4];
            u64 b0 = rep2(b4.x), b1 = rep2(b4.y), b2 = rep2(b4.z), b3 = rep2(b4.w);
            fma2(acc[0][0], a0, b0); fma2(acc[0][1], a0, b1); fma2(acc[0][2], a0, b2); fma2(acc[0][3], a0, b3);
            fma2(acc[1][0], a1, b0); fma2(acc[1][1], a1, b1); fma2(acc[1][2], a1, b2); fma2(acc[1][3], a1, b3);
            fma2(acc[2][0], a2, b0); fma2(acc[2][1], a2, b1); fma2(acc[2][2], a2, b2); fma2(acc[2][3], a2, b3);
            fma2(acc[3][0], a3, b0); fma2(acc[3][1], a3, b1); fma2(acc[3][2], a3, b2); fma2(acc[3][3], a3, b3);
        }
        __syncthreads();
    }

    const int gbase = gt * 64 + tc * 4;
    float bias[4];
#pragma unroll
    for (int j = 0; j < 4; j++) bias[j] = bi[gbase + j] + bh[gbase + j];

    float* outp = g_xp + (((size_t)dir * T_ + t) * B_) * G4;
#pragma unroll
    for (int i = 0; i < 8; i++) {
        int m = tr * 8 + i;
        int p = i >> 1;
        float v0 = (i & 1) ? hi32(acc[p][0]) : lo32(acc[p][0]);
        float v1 = (i & 1) ? hi32(acc[p][1]) : lo32(acc[p][1]);
        float v2 = (i & 1) ? hi32(acc[p][2]) : lo32(acc[p][2]);
        float v3 = (i & 1) ? hi32(acc[p][3]) : lo32(acc[p][3]);
        float4 v = make_float4(v0 + bias[0], v1 + bias[1], v2 + bias[2], v3 + bias[3]);
        *(float4*)(outp + (size_t)m * G4 + gbase) = v;
    }
}

// ---------------------------------------------------------------------------
// Persistent LSTM recurrence kernel.
// grid=128 (dir,jt fixed per CTA), block=256 (8 warps).
// Split-K: warps 0-3 -> k[0,512), warps 4-7 -> k[512,1024); each group uses
// R2's 8x4 microtile over the 64x64 tile. A via 4-deep cp.async.cg ring
// (coherent, L1-bypassing); B via __ldg (L1-resident across steps within the
// single launch). Grid barrier (sense = step counter) between steps.
// Shared: sA ring 4*2*16*64 floats (32KB), reused as sG[64*65] after wait0.
// ---------------------------------------------------------------------------
#define SA_RING_FLOATS (4 * 2 * BKH * 64)    // 8192 floats = 32 KB
#define SG_STRIDE 65

__global__ void __launch_bounds__(256, 1) lstm_persistent_kernel(float* __restrict__ out)
{
    __shared__ float smem[SA_RING_FLOATS];   // 32 KB, sA ring; aliased as sG later

    const int bx  = blockIdx.x;
    const int dir = bx & 1;
    const int jt  = bx >> 1;                 // 0..63

    const int tid  = threadIdx.x;
    const int grp  = tid >> 7;               // 0 or 1 (half-K group)
    const int ltid = tid & 127;
    const int tr   = ltid >> 4;              // 0..7
    const int tc   = ltid & 15;              // 0..15

    float*       cT  = &g_cT[dir][0][0];
    const float* wT  = &g_wT[dir][0][0];

    const u32 sA_u = (u32)__cvta_generic_to_shared(smem);

    // B column base for this thread (global gate col of its 4 cols)
    const int q    = tc >> 2;
    const int jj   = (tc & 3) * 4;
    const int gcol = q * H_ + jt * 16 + jj;       // also == sG col mapping tc*4
    const float* Bcol = wT + (size_t)grp * 512 * G4 + gcol;

    for (int t = 0; t < T_; t++) {
        const int phase = t & 1;
        const float* hT  = &g_hT[phase][dir][0][0];
        float*       hTn = &g_hT[phase ^ 1][dir][0][0];
        const float* xp  = g_xp + ((size_t)dir * T_ + t) * B_ * G4;

        u64 acc[4][4];
#pragma unroll
        for (int p = 0; p < 4; p++)
#pragma unroll
            for (int j = 0; j < 4; j++) acc[p][j] = 0ull;

        // ---- A-stage issue helper (inline): stage s covers k grp*512 + s*16 .. +16
        // layout: smem[buf][grp][kk][m], buf stride 2048 floats, grp stride 1024
        // 512 chunks of 16B per stage; thread does chunks tid and tid+256
        // chunk c: grp_c = c>>8, idx = c&255 -> float offset idx*4 within grp slice
        // src: hT + (grp_c*512 + s*16)*64 + idx*4  (contiguous 4KB per grp)
#define ISSUE_A(s) do {                                                          \
            const int _s = (s);                                                  \
            const u32 dst = sA_u + (u32)(((_s) & 3) * 2048 * 4);                 \
            cp_async16(dst + (u32)tid * 16,                                      \
                       hT + (size_t)(_s) * BKH * 64 + (tid & 255) * 4            \
                          + (size_t)(tid >> 8) * 0);                             \
            cp_async16(dst + 4096 + (u32)tid * 16,                               \
                       hT + (size_t)(512 + (_s) * BKH) * 64 + tid * 4);          \
            cp_commit();                                                         \
        } while (0)

        ISSUE_A(0);
        ISSUE_A(1);

        // first B prefetch
        float4 bnext = *(const float4*)(Bcol + 0 * G4);

        for (int s = 0; s < NSTAGE; s++) {
            if (s + 2 < NSTAGE) { ISSUE_A(s + 2); cp_wait(2); }
            else if (s + 1 < NSTAGE) cp_wait(1);
            else cp_wait(0);
            __syncthreads();

            const float* A = smem + (s & 3) * 2048 + grp * 1024 + tr * 8;
            const int kbase = s * BKH;   // within group's 512-range
#pragma unroll
            for (int kk = 0; kk < BKH; kk++) {
                float4 b4 = bnext;
                {   // prefetch next B
                    int knl = kbase + kk + 1;
                    if (knl < 512)
                        bnext = *(const float4*)(Bcol + (size_t)knl * G4);
                }
                const float* ap = A + kk * 64;
                u64 a0 = *(const u64*)(ap + 0);
                u64 a1 = *(const u64*)(ap + 2);
                u64 a2 = *(const u64*)(ap + 4);
                u64 a3 = *(const u64*)(ap + 6);
                u64 b0 = rep2(b4.x), b1 = rep2(b4.y), b2 = rep2(b4.z), b3 = rep2(b4.w);
                fma2(acc[0][0], a0, b0); fma2(acc[0][1], a0, b1); fma2(acc[0][2], a0, b2); fma2(acc[0][3], a0, b3);
                fma2(acc[1][0], a1, b0); fma2(acc[1][1], a1, b1); fma2(acc[1][2], a1, b2); fma2(acc[1][3], a1, b3);
                fma2(acc[2][0], a2, b0); fma2(acc[2][1], a2, b1); fma2(acc[2][2], a2, b2); fma2(acc[2][3], a2, b3);
                fma2(acc[3][0], a3, b0); fma2(acc[3][1], a3, b1); fma2(acc[3][2], a3, b2); fma2(acc[3][3], a3, b3);
            }
            __syncthreads();   // stage s fully consumed before refill of (s+... ) next iter
        }
        // re-arm B prefetch for next timestep
        // (bnext currently holds k=511 garbage-path value; reload cleanly)
        bnext = *(const float4*)(Bcol + 0 * G4);

        // ---- reduction + gates ----
        float* sG = smem;   // alias ring (all cp.async complete: wait(0) above)
        // group 1 writes partials
        if (grp == 1) {
#pragma unroll
            for (int i = 0; i < 8; i++) {
                int m = tr * 8 + i;
                int p = i >> 1;
                float v0 = (i & 1) ? hi32(acc[p][0]) : lo32(acc[p][0]);
                float v1 = (i & 1) ? hi32(acc[p][1]) : lo32(acc[p][1]);
                float v2 = (i & 1) ? hi32(acc[p][2]) : lo32(acc[p][2]);
                float v3 = (i & 1) ? hi32(acc[p][3]) : lo32(acc[p][3]);
                float* d = sG + m * SG_STRIDE + tc * 4;
                d[0] = v0; d[1] = v1; d[2] = v2; d[3] = v3;
            }
        }
        __syncthreads();
        // group 0 adds own acc + partial + xp -> final gate values in sG
        if (grp == 0) {
#pragma unroll
            for (int i = 0; i < 8; i++) {
                int m = tr * 8 + i;
                int p = i >> 1;
                float v0 = (i & 1) ? hi32(acc[p][0]) : lo32(acc[p][0]);
                float v1 = (i & 1) ? hi32(acc[p][1]) : lo32(acc[p][1]);
                float v2 = (i & 1) ? hi32(acc[p][2]) : lo32(acc[p][2]);
                float v3 = (i & 1) ? hi32(acc[p][3]) : lo32(acc[p][3]);
                float4 xv = *(const float4*)(xp + (size_t)m * G4 + gcol);
                float* d = sG + m * SG_STRIDE + tc * 4;
                d[0] += v0 + xv.x;
                d[1] += v1 + xv.y;
                d[2] += v2 + xv.z;
                d[3] += v3 + xv.w;
            }
        }
        __syncthreads();

        // ---- activation + state update (all 256 threads, 4 cells each) ----
#pragma unroll
        for (int p4 = tid; p4 < 1024; p4 += 256) {
            int b = p4 >> 4, j = p4 & 15;
            float ig = sG[b * SG_STRIDE + j];
            float fg = sG[b * SG_STRIDE + 16 + j];
            float gg = sG[b * SG_STRIDE + 32 + j];
            float og = sG[b * SG_STRIDE + 48 + j];
            int jc = jt * 16 + j;

            float c_old = cT[jc * B_ + b];
            float si = 1.0f / (1.0f + __expf(-ig));
            float sf = 1.0f / (1.0f + __expf(-fg));
            float so = 1.0f / (1.0f + __expf(-og));
            float cn = sf * c_old + si * tanhf(gg);
            float hn = so * tanhf(cn);

            cT[jc * B_ + b]  = cn;
            hTn[jc * B_ + b] = hn;
            out[((size_t)b * T_ + t) * (2 * H_) + dir * H_ + jc] = hn;

            if (t == T_ - 1) {     // fold finalize
                const size_t base = (size_t)B_ * T_ * 2 * H_;
                out[base + (dir ? 2 : 0) * (size_t)BH + b * H_ + jc] = hn;
                out[base + (dir ? 3 : 1) * (size_t)BH + b * H_ + jc] = cn;
            }
        }

        // ---- grid barrier (sense = monotonically increasing step count) ----
        __syncthreads();
        if (tid == 0) {
            __threadfence();
            unsigned ticket = atomicAdd(&g_bar_count, 1u);
            if (ticket == NCTA - 1) {
                g_bar_count = 0;
                __threadfence();
                g_bar_sense = (unsigned)(t + 1);
            } else {
                while (g_bar_sense < (unsigned)(t + 1)) { __nanosleep(64); }
            }
            __threadfence();
        }
        __syncthreads();
#undef ISSUE_A
    }
}

// ---------------------------------------------------------------------------
// Launch
// ---------------------------------------------------------------------------
extern "C" void kernel_launch(void* const* d_in, const int* in_sizes, int n_in,
                              void* d_out, int out_size) {
    (void)in_sizes; (void)n_in; (void)out_size;
    const float* x       = (const float*)d_in[0];
    const float* w_ih_fw = (const float*)d_in[1];
    const float* w_hh_fw = (const float*)d_in[2];
    const float* b_ih_fw = (const float*)d_in[3];
    const float* b_hh_fw = (const float*)d_in[4];
    const float* w_ih_bw = (const float*)d_in[5];
    const float* w_hh_bw = (const float*)d_in[6];
    const float* b_ih_bw = (const float*)d_in[7];
    const float* b_hh_bw = (const float*)d_in[8];
    float* out = (float*)d_out;

    init_state_kernel<<<(2 * BH + 255) / 256, 256>>>();

    dim3 gtw(G4 / 32, H_ / 32, 2);
    transpose_w_kernel<<<gtw, 256>>>(w_hh_fw, w_hh_bw);

    dim3 gproj(64, T_, 2);
    input_proj_kernel<<<gproj, 128>>>(x, w_ih_fw, w_ih_bw,
                                      b_ih_fw, b_hh_fw, b_ih_bw, b_hh_bw);

    lstm_persistent_kernel<<<NCTA, 256>>>(out);
}

// round 6
// speedup vs baseline: 2.5180x; 2.5180x over previous
#include <cuda_runtime.h>
#include <cuda_bf16.h>
#include <math.h>

// Problem constants
#define B_  64
#define T_  512
#define I_  512
#define H_  1024
#define G4  4096           // 4*H
#define BH  (B_*H_)        // 65536
#define NCTA 128
#define BK  32
#define NSTAGE (H_/BK)     // 32

typedef unsigned long long u64;
typedef unsigned int u32;

// ---------------------------------------------------------------------------
// Device scratch
// ---------------------------------------------------------------------------
__device__ float g_xp[(size_t)2 * T_ * B_ * G4];   // xp[dir][t][b][g]  (1 GiB)
__device__ float g_wT[2][H_][G4];                  // w_hh transposed [dir][k][n] (32 MB)
__device__ float g_hT[2][2][H_][B_];               // h: [phase][dir][j][b]
__device__ unsigned g_bar_count;
__device__ volatile unsigned g_bar_sense;

// ---------------------------------------------------------------------------
// PTX helpers
// ---------------------------------------------------------------------------
__device__ __forceinline__ void fma2(u64& c, u64 a, u64 b) {
    asm volatile("fma.rn.f32x2 %0, %1, %2, %0;" : "+l"(c) : "l"(a), "l"(b));
}
__device__ __forceinline__ u64 rep2(float x) {
    u64 r;
    asm volatile("mov.b64 %0, {%1, %1};" : "=l"(r) : "f"(x));
    return r;
}
__device__ __forceinline__ void cp_async16(u32 smem_addr, const void* gptr) {
    asm volatile("cp.async.cg.shared.global [%0], [%1], 16;" :: "r"(smem_addr), "l"(gptr));
}
__device__ __forceinline__ void cp_commit() { asm volatile("cp.async.commit_group;"); }
__device__ __forceinline__ void cp_wait1()  { asm volatile("cp.async.wait_group 1;"); }
__device__ __forceinline__ void cp_wait0()  { asm volatile("cp.async.wait_group 0;"); }
__device__ __forceinline__ float lo32(u64 v) { return __uint_as_float((u32)(v & 0xffffffffull)); }
__device__ __forceinline__ float hi32(u64 v) { return __uint_as_float((u32)(v >> 32)); }

// ---------------------------------------------------------------------------
// Init (every replay): zero h(phase 0) and barrier state
// ---------------------------------------------------------------------------
__global__ void init_state_kernel() {
    int i = blockIdx.x * blockDim.x + threadIdx.x;
    if (i < 2 * BH) ((float*)g_hT)[i] = 0.0f;
    if (i == 0) { g_bar_count = 0; g_bar_sense = 0; }
}

// ---------------------------------------------------------------------------
// Transpose w_hh [4096,1024] -> g_wT [dir][1024][4096]
// ---------------------------------------------------------------------------
__global__ void __launch_bounds__(256) transpose_w_kernel(
    const float* __restrict__ wfw, const float* __restrict__ wbw)
{
    __shared__ float tile[32][33];
    const int dir = blockIdx.z;
    const float* w = dir ? wbw : wfw;
    const int n0 = blockIdx.x * 32;
    const int k0 = blockIdx.y * 32;
    const int tx = threadIdx.x & 31, ty = threadIdx.x >> 5;
#pragma unroll
    for (int r = 0; r < 32; r += 8)
        tile[ty + r][tx] = w[(size_t)(n0 + ty + r) * H_ + k0 + tx];
    __syncthreads();
#pragma unroll
    for (int r = 0; r < 32; r += 8)
        g_wT[dir][k0 + ty + r][n0 + tx] = tile[tx][ty + r];
}

// ---------------------------------------------------------------------------
// Input projection (R2 version — known good)
// ---------------------------------------------------------------------------
__global__ void __launch_bounds__(128) input_proj_kernel(
    const float* __restrict__ x,
    const float* __restrict__ w_fw, const float* __restrict__ w_bw,
    const float* __restrict__ bi_fw, const float* __restrict__ bh_fw,
    const float* __restrict__ bi_bw, const float* __restrict__ bh_bw)
{
    const int gt  = blockIdx.x;
    const int t   = blockIdx.y;
    const int dir = blockIdx.z;

    const float* w     = dir ? w_bw : w_fw;
    const float* bi    = dir ? bi_bw : bi_fw;
    const float* bh    = dir ? bh_bw : bh_fw;
    const int    src_t = dir ? (T_ - 1 - t) : t;

    __shared__ float sA[16][68];
    __shared__ float sB[16][68];

    const int tid = threadIdx.x;
    const int tr  = tid >> 4;
    const int tc  = tid & 15;

    u64 acc[4][4];
#pragma unroll
    for (int p = 0; p < 4; p++)
#pragma unroll
        for (int j = 0; j < 4; j++) acc[p][j] = 0ull;

    const float* Abase = x + (size_t)src_t * I_;
    const float* Bbase = w + (size_t)(gt * 64) * I_;

    for (int k0 = 0; k0 < I_; k0 += 16) {
#pragma unroll 4
        for (int idx = tid; idx < 1024; idx += 128) {
            int kk = idx & 15, m = idx >> 4;
            sA[kk][m] = Abase[(size_t)m * (T_ * I_) + k0 + kk];
        }
#pragma unroll 4
        for (int idx = tid; idx < 1024; idx += 128) {
            int kk = idx & 15, n = idx >> 4;
            sB[kk][n] = Bbase[(size_t)n * I_ + k0 + kk];
        }
        __syncthreads();
#pragma unroll
        for (int kk = 0; kk < 16; kk++) {
            const float* ap = &sA[kk][tr * 8];
            u64 a0 = *(const u64*)(ap + 0);
            u64 a1 = *(const u64*)(ap + 2);
            u64 a2 = *(const u64*)(ap + 4);
            u64 a3 = *(const u64*)(ap + 6);
            float4 b4 = *(const float4*)&sB[kk][tc * 4];
            u64 b0 = rep2(b4.x), b1 = rep2(b4.y), b2 = rep2(b4.z), b3 = rep2(b4.w);
            fma2(acc[0][0], a0, b0); fma2(acc[0][1], a0, b1); fma2(acc[0][2], a0, b2); fma2(acc[0][3], a0, b3);
            fma2(acc[1][0], a1, b0); fma2(acc[1][1], a1, b1); fma2(acc[1][2], a1, b2); fma2(acc[1][3], a1, b3);
            fma2(acc[2][0], a2, b0); fma2(acc[2][1], a2, b1); fma2(acc[2][2], a2, b2); fma2(acc[2][3], a2, b3);
            fma2(acc[3][0], a3, b0); fma2(acc[3][1], a3, b1); fma2(acc[3][2], a3, b2); fma2(acc[3][3], a3, b3);
        }
        __syncthreads();
    }

    const int gbase = gt * 64 + tc * 4;
    float bias[4];
#pragma unroll
    for (int j = 0; j < 4; j++) bias[j] = bi[gbase + j] + bh[gbase + j];

    float* outp = g_xp + (((size_t)dir * T_ + t) * B_) * G4;
#pragma unroll
    for (int i = 0; i < 8; i++) {
        int m = tr * 8 + i;
        int p = i >> 1;
        float v0 = (i & 1) ? hi32(acc[p][0]) : lo32(acc[p][0]);
        float v1 = (i & 1) ? hi32(acc[p][1]) : lo32(acc[p][1]);
        float v2 = (i & 1) ? hi32(acc[p][2]) : lo32(acc[p][2]);
        float v3 = (i & 1) ? hi32(acc[p][3]) : lo32(acc[p][3]);
        float4 v = make_float4(v0 + bias[0], v1 + bias[1], v2 + bias[2], v3 + bias[3]);
        *(float4*)(outp + (size_t)m * G4 + gbase) = v;
    }
}

// ---------------------------------------------------------------------------
// Persistent LSTM recurrence.
// grid=128 (dir,jt per CTA), block=256 (8 warps, all full-K on 64x64 tile).
// Microtile: warp w owns b rows w*8..w*8+7; lane l owns cols n=2l,2l+1.
// Both operands bulk-staged via cp.async (triple-buffered, 1 sync/stage).
// c state in registers (4 cells/thread). Grid barrier between steps.
// smem: sA[3][32*64] | sB[3][32*64]  (48 KB); sG[64*66] aliases sA.
// ---------------------------------------------------------------------------
#define SA_FLOATS (3 * BK * 64)    // 6144
#define SB_FLOATS (3 * BK * 64)    // 6144
#define SG_STRIDE 66               // EVEN -> 8B-aligned float2 rows (R5 bug: 65)

__global__ void __launch_bounds__(256, 1) lstm_persistent_kernel(float* __restrict__ out)
{
    __shared__ float smem[SA_FLOATS + SB_FLOATS];   // 48 KB
    float* sA = smem;
    float* sB = smem + SA_FLOATS;
    float* sG = smem;                                // alias sA after drain (64*66=4224<=6144)

    const int bx  = blockIdx.x;
    const int dir = bx & 1;
    const int jt  = bx >> 1;                 // 0..63

    const int tid  = threadIdx.x;
    const int w    = tid >> 5;               // warp 0..7
    const int l    = tid & 31;               // lane

    const float* wT = &g_wT[dir][0][0];
    const u32 sA_u = (u32)__cvta_generic_to_shared(sA);
    const u32 sB_u = (u32)__cvta_generic_to_shared(sB);

    // B cp.async source pieces for this thread's 2 chunks:
    const int c0_kk = tid >> 4;
    const int c1_kk = c0_kk + 16;
    const int c0_pc = tid & 15;
    const int pc_q = c0_pc >> 2, pc_s = c0_pc & 3;
    const size_t bcol_off = (size_t)(pc_q * H_ + jt * 16 + pc_s * 4);
    const u32 b_sm_off = (u32)((pc_q * 16 + pc_s * 4) * 4);

    // register c state: cells p4 = tid + r*256, r=0..3
    float creg[4];
#pragma unroll
    for (int r = 0; r < 4; r++) creg[r] = 0.0f;

    for (int t = 0; t < T_; t++) {
        const int phase = t & 1;
        const float* hT  = &g_hT[phase][dir][0][0];
        float*       hTn = &g_hT[phase ^ 1][dir][0][0];
        const float* xp  = g_xp + ((size_t)dir * T_ + t) * B_ * G4;

        u64 acc[4][2];
#pragma unroll
        for (int p = 0; p < 4; p++) { acc[p][0] = 0ull; acc[p][1] = 0ull; }

#define ISSUE(s) do {                                                             \
            const int _s = (s);                                                   \
            const int _buf = _s % 3;                                              \
            const u32 _ad = sA_u + (u32)(_buf * BK * 64 * 4);                     \
            const u32 _bd = sB_u + (u32)(_buf * BK * 64 * 4);                     \
            cp_async16(_ad + (u32)tid * 16,        hT + (size_t)_s * 2048 + tid * 4);        \
            cp_async16(_ad + (u32)tid * 16 + 4096, hT + (size_t)_s * 2048 + 1024 + tid * 4); \
            cp_async16(_bd + (u32)(c0_kk * 256) + b_sm_off,                       \
                       wT + (size_t)(_s * BK + c0_kk) * G4 + bcol_off);           \
            cp_async16(_bd + (u32)(c1_kk * 256) + b_sm_off,                       \
                       wT + (size_t)(_s * BK + c1_kk) * G4 + bcol_off);           \
            cp_commit();                                                          \
        } while (0)

        ISSUE(0);
        ISSUE(1);

        for (int s = 0; s < NSTAGE; s++) {
            if (s + 1 < NSTAGE) cp_wait1(); else cp_wait0();
            __syncthreads();                 // stage s ready; all done with s-1
            if (s + 2 < NSTAGE) ISSUE(s + 2);   // buf (s+2)%3 == (s-1)%3: safe

            const float* A  = sA + (s % 3) * (BK * 64) + w * 8;
            const float* Bm = sB + (s % 3) * (BK * 64) + 2 * l;
#pragma unroll
            for (int kk = 0; kk < BK; kk++) {
                const float* ap = A + kk * 64;          // warp-uniform -> broadcast
                u64 a0 = *(const u64*)(ap + 0);
                u64 a1 = *(const u64*)(ap + 2);
                u64 a2 = *(const u64*)(ap + 4);
                u64 a3 = *(const u64*)(ap + 6);
                float2 bw = *(const float2*)(Bm + kk * 64);
                u64 b0 = rep2(bw.x), b1 = rep2(bw.y);
                fma2(acc[0][0], a0, b0); fma2(acc[0][1], a0, b1);
                fma2(acc[1][0], a1, b0); fma2(acc[1][1], a1, b1);
                fma2(acc[2][0], a2, b0); fma2(acc[2][1], a2, b1);
                fma2(acc[3][0], a3, b0); fma2(acc[3][1], a3, b1);
            }
        }
#undef ISSUE

        // ---- stage raw GEMM sums into sG[64][66] (aliases sA; all drained) ----
        // acc[p][j]: lo = cell(b=w*8+2p, n=2l+j), hi = cell(b=w*8+2p+1, n=2l+j)
#pragma unroll
        for (int p = 0; p < 4; p++) {
            int m0 = w * 8 + 2 * p;
            float2 v_lo = make_float2(lo32(acc[p][0]), lo32(acc[p][1]));
            float2 v_hi = make_float2(hi32(acc[p][0]), hi32(acc[p][1]));
            *(float2*)(sG + (m0 + 0) * SG_STRIDE + 2 * l) = v_lo;
            *(float2*)(sG + (m0 + 1) * SG_STRIDE + 2 * l) = v_hi;
        }
        __syncthreads();

        // ---- activation + state update: cells p4 = tid + r*256 ----
#pragma unroll
        for (int r = 0; r < 4; r++) {
            int p4 = tid + r * 256;
            int b = p4 >> 4, j = p4 & 15;
            int jc = jt * 16 + j;
            const float* xpb = xp + (size_t)b * G4 + jt * 16 + j;

            float ig = sG[b * SG_STRIDE +      j] + xpb[0 * H_];
            float fg = sG[b * SG_STRIDE + 16 + j] + xpb[1 * H_];
            float gg = sG[b * SG_STRIDE + 32 + j] + xpb[2 * H_];
            float og = sG[b * SG_STRIDE + 48 + j] + xpb[3 * H_];

            float si = 1.0f / (1.0f + __expf(-ig));
            float sf = 1.0f / (1.0f + __expf(-fg));
            float so = 1.0f / (1.0f + __expf(-og));
            float cn = sf * creg[r] + si * tanhf(gg);
            float hn = so * tanhf(cn);
            creg[r] = cn;

            hTn[jc * B_ + b] = hn;
            out[((size_t)b * T_ + t) * (2 * H_) + dir * H_ + jc] = hn;

            if (t == T_ - 1) {
                const size_t base = (size_t)B_ * T_ * 2 * H_;
                out[base + (dir ? 2 : 0) * (size_t)BH + b * H_ + jc] = hn;
                out[base + (dir ? 3 : 1) * (size_t)BH + b * H_ + jc] = cn;
            }
        }

        // ---- grid barrier ----
        __threadfence();                    // publish h stores (all threads)
        __syncthreads();
        if (tid == 0) {
            unsigned ticket = atomicAdd(&g_bar_count, 1u);
            if (ticket == NCTA - 1) {
                g_bar_count = 0;
                __threadfence();
                g_bar_sense = (unsigned)(t + 1);
            } else {
                while (g_bar_sense < (unsigned)(t + 1)) { __nanosleep(32); }
            }
        }
        __syncthreads();
    }
}

// ---------------------------------------------------------------------------
// Launch
// ---------------------------------------------------------------------------
extern "C" void kernel_launch(void* const* d_in, const int* in_sizes, int n_in,
                              void* d_out, int out_size) {
    (void)in_sizes; (void)n_in; (void)out_size;
    const float* x       = (const float*)d_in[0];
    const float* w_ih_fw = (const float*)d_in[1];
    const float* w_hh_fw = (const float*)d_in[2];
    const float* b_ih_fw = (const float*)d_in[3];
    const float* b_hh_fw = (const float*)d_in[4];
    const float* w_ih_bw = (const float*)d_in[5];
    const float* w_hh_bw = (const float*)d_in[6];
    const float* b_ih_bw = (const float*)d_in[7];
    const float* b_hh_bw = (const float*)d_in[8];
    float* out = (float*)d_out;

    init_state_kernel<<<(2 * BH + 255) / 256, 256>>>();

    dim3 gtw(G4 / 32, H_ / 32, 2);
    transpose_w_kernel<<<gtw, 256>>>(w_hh_fw, w_hh_bw);

    dim3 gproj(64, T_, 2);
    input_proj_kernel<<<gproj, 128>>>(x, w_ih_fw, w_ih_bw,
                                      b_ih_fw, b_hh_fw, b_ih_bw, b_hh_bw);

    lstm_persistent_kernel<<<NCTA, 256>>>(out);
}